// round 13
// baseline (speedup 1.0000x reference)
#include <cuda_runtime.h>
#include <cstdint>

#define N_GRAPHS 1024
#define N_NODES  65536
#define N_EDGES  262144
#define D        256
#define D_IN     768
#define D_HID    512
#define D_OUT    256

// Scratch (no allocations allowed)
__device__ float g_collected[N_GRAPHS * D_IN];
__device__ float g_hidden[N_GRAPHS * D_HID];
__device__ int   g_eoff[N_GRAPHS + 1];
__device__ int   g_noff[N_GRAPHS + 1];

// ---------------------------------------------------------------------------
// Kernel 0: one-shot boundary precompute (2050 parallel binary searches).
// ---------------------------------------------------------------------------
__global__ void bounds_kernel(const int* __restrict__ eids,
                              const int* __restrict__ nids)
{
    const int t = blockIdx.x * blockDim.x + threadIdx.x;
    if (t <= N_GRAPHS) {
        int lo = 0, hi = N_EDGES;
        while (lo < hi) {
            int m = (lo + hi) >> 1;
            if (eids[m] < t) lo = m + 1; else hi = m;
        }
        g_eoff[t] = lo;
    } else if (t <= 2 * N_GRAPHS + 1) {
        const int g = t - (N_GRAPHS + 1);
        int lo = 0, hi = N_NODES;
        while (lo < hi) {
            int m = (lo + hi) >> 1;
            if (nids[m] < g) lo = m + 1; else hi = m;
        }
        g_noff[g] = lo;
    }
}

// ---------------------------------------------------------------------------
// Kernel 1: segment sums + concat. 8 CTAs/graph, precomputed bounds.
// 256 threads = 32 row-lanes x 8 float4-cols. Shuffle + smem reduce.
// ---------------------------------------------------------------------------
__global__ __launch_bounds__(256) void collect_kernel(
    const float4* __restrict__ nodes,
    const float4* __restrict__ edges,
    const float4* __restrict__ globals_,
    float4* __restrict__ collected4)
{
    const int g     = blockIdx.x >> 3;
    const int chunk = blockIdx.x & 7;
    const int t     = threadIdx.x;
    const int c     = t & 7;
    const int rl    = t >> 3;
    const int lane  = t & 31;
    const int wid   = t >> 5;
    const int colf4 = chunk * 8 + c;

    __shared__ float4 red_e[8][8];
    __shared__ float4 red_n[8][8];

    const int elo = __ldg(&g_eoff[g]), ehi = __ldg(&g_eoff[g + 1]);
    const int nlo = __ldg(&g_noff[g]), nhi = __ldg(&g_noff[g + 1]);

    float4 eacc = make_float4(0.f, 0.f, 0.f, 0.f);
    #pragma unroll 8
    for (int r = elo + rl; r < ehi; r += 32) {
        float4 v = __ldcs(&edges[(size_t)r * (D / 4) + colf4]);
        eacc.x += v.x; eacc.y += v.y; eacc.z += v.z; eacc.w += v.w;
    }
    float4 nacc = make_float4(0.f, 0.f, 0.f, 0.f);
    #pragma unroll 4
    for (int r = nlo + rl; r < nhi; r += 32) {
        float4 v = __ldcs(&nodes[(size_t)r * (D / 4) + colf4]);
        nacc.x += v.x; nacc.y += v.y; nacc.z += v.z; nacc.w += v.w;
    }

    #pragma unroll
    for (int s = 8; s <= 16; s <<= 1) {
        eacc.x += __shfl_xor_sync(0xffffffffu, eacc.x, s);
        eacc.y += __shfl_xor_sync(0xffffffffu, eacc.y, s);
        eacc.z += __shfl_xor_sync(0xffffffffu, eacc.z, s);
        eacc.w += __shfl_xor_sync(0xffffffffu, eacc.w, s);
        nacc.x += __shfl_xor_sync(0xffffffffu, nacc.x, s);
        nacc.y += __shfl_xor_sync(0xffffffffu, nacc.y, s);
        nacc.z += __shfl_xor_sync(0xffffffffu, nacc.z, s);
        nacc.w += __shfl_xor_sync(0xffffffffu, nacc.w, s);
    }
    if (lane < 8) { red_e[wid][lane] = eacc; red_n[wid][lane] = nacc; }
    __syncthreads();

    if (t < 8) {
        float4 s = red_e[0][t];
        #pragma unroll
        for (int i = 1; i < 8; ++i) {
            float4 v = red_e[i][t];
            s.x += v.x; s.y += v.y; s.z += v.z; s.w += v.w;
        }
        collected4[(size_t)g * (D_IN / 4) + chunk * 8 + t] = s;
    } else if (t < 16) {
        const int cc = t - 8;
        float4 s = red_n[0][cc];
        #pragma unroll
        for (int i = 1; i < 8; ++i) {
            float4 v = red_n[i][cc];
            s.x += v.x; s.y += v.y; s.z += v.z; s.w += v.w;
        }
        collected4[(size_t)g * (D_IN / 4) + (D / 4) + chunk * 8 + cc] = s;
    } else if (t < 24) {
        const int cc = t - 16;
        collected4[(size_t)g * (D_IN / 4) + 2 * (D / 4) + chunk * 8 + cc] =
            globals_[(size_t)g * (D / 4) + chunk * 8 + cc];
    }
}

// ---------------------------------------------------------------------------
// Kernel 2: TF32 MMA GEMM, 256 threads / 8 warps, BM=BN=64, BK=16,
// 4-STAGE cp.async pipeline. Invariant: exactly ONE commit_group per
// iteration (empty at the tail) so wait_group STAGES-2 always guarantees
// the stage about to be consumed has landed.
// ---------------------------------------------------------------------------
__device__ __forceinline__ unsigned f2tf32(float x) {
    unsigned r;
    asm("cvt.rna.tf32.f32 %0, %1;" : "=r"(r) : "f"(x));
    return r;
}

__device__ __forceinline__ void mma_tf32(float (&c)[4],
                                         const unsigned (&a)[4],
                                         const unsigned (&b)[2]) {
    asm volatile(
        "mma.sync.aligned.m16n8k8.row.col.f32.tf32.tf32.f32 "
        "{%0,%1,%2,%3}, {%4,%5,%6,%7}, {%8,%9}, {%0,%1,%2,%3};\n"
        : "+f"(c[0]), "+f"(c[1]), "+f"(c[2]), "+f"(c[3])
        : "r"(a[0]), "r"(a[1]), "r"(a[2]), "r"(a[3]),
          "r"(b[0]), "r"(b[1]));
}

__device__ __forceinline__ void cp_async16(void* smem_dst, const void* gmem_src) {
    unsigned s = (unsigned)__cvta_generic_to_shared(smem_dst);
    asm volatile("cp.async.cg.shared.global [%0], [%1], 16;\n"
                 :: "r"(s), "l"(gmem_src));
}

template <bool RELU>
__global__ __launch_bounds__(256) void mma_gemm(
    const float* __restrict__ A,
    const float* __restrict__ B,
    const float* __restrict__ bias,
    float* __restrict__ C,
    int M, int N, int K)
{
    constexpr int BM = 64, BN = 64, BK = 16;
    constexpr int STAGES = 4;
    constexpr int AS = BK + 4;   // 20 floats -> 80B rows (16B aligned)
    constexpr int BS = BN + 8;   // 72 floats -> 288B rows (16B aligned)
    __shared__ float As[STAGES][BM][AS];
    __shared__ float Bs[STAGES][BK][BS];

    const int tid  = threadIdx.x;
    const int wid  = tid >> 5;
    const int lane = tid & 31;
    const int gid  = lane >> 2;
    const int tig  = lane & 3;
    const int m0 = blockIdx.y * BM;
    const int n0 = blockIdx.x * BN;
    const int wm = (wid & 1) * 32;        // 2 warps along m
    const int wn = (wid >> 1) * 16;       // 4 warps along n

    float c[2][2][4];
    #pragma unroll
    for (int i = 0; i < 2; ++i)
        #pragma unroll
        for (int j = 0; j < 2; ++j)
            #pragma unroll
            for (int q = 0; q < 4; ++q) c[i][j][q] = 0.f;

    auto load_stage = [&](int buf, int k0) {
        // A: 64x16 f32 = 256 float4, 1 per thread
        {
            int r = tid >> 2, c4 = tid & 3;
            cp_async16(&As[buf][r][c4 * 4],
                       &A[(size_t)(m0 + r) * K + k0 + c4 * 4]);
        }
        // B: 16x64 f32 = 256 float4, 1 per thread
        {
            int r = tid >> 4, c4 = tid & 15;
            cp_async16(&Bs[buf][r][c4 * 4],
                       &B[(size_t)(k0 + r) * N + n0 + c4 * 4]);
        }
        asm volatile("cp.async.commit_group;\n" ::: "memory");
    };

    const int n_iter = K / BK;
    #pragma unroll
    for (int s = 0; s < STAGES - 1; ++s)
        load_stage(s, s * BK);            // K >= 3*BK always here

    for (int it = 0; it < n_iter; ++it) {
        asm volatile("cp.async.wait_group %0;\n" :: "n"(STAGES - 2) : "memory");
        __syncthreads();                  // stage `it` landed; prev buf free
        const int nxt = it + STAGES - 1;
        if (nxt < n_iter) {
            load_stage(nxt & (STAGES - 1), nxt * BK);
        } else {
            // Tail: keep the one-commit-per-iteration invariant so the
            // wait_group count above still proves stage `it` has landed.
            asm volatile("cp.async.commit_group;\n" ::: "memory");
        }
        const int buf = it & (STAGES - 1);

        #pragma unroll
        for (int ks = 0; ks < BK; ks += 8) {
            unsigned a[2][4], b[2][2];
            #pragma unroll
            for (int mt = 0; mt < 2; ++mt) {
                const int rb = wm + mt * 16 + gid;
                a[mt][0] = f2tf32(As[buf][rb][ks + tig]);
                a[mt][1] = f2tf32(As[buf][rb + 8][ks + tig]);
                a[mt][2] = f2tf32(As[buf][rb][ks + tig + 4]);
                a[mt][3] = f2tf32(As[buf][rb + 8][ks + tig + 4]);
            }
            #pragma unroll
            for (int nt = 0; nt < 2; ++nt) {
                const int cb = wn + nt * 8 + gid;
                b[nt][0] = f2tf32(Bs[buf][ks + tig][cb]);
                b[nt][1] = f2tf32(Bs[buf][ks + tig + 4][cb]);
            }
            #pragma unroll
            for (int mt = 0; mt < 2; ++mt)
                #pragma unroll
                for (int nt = 0; nt < 2; ++nt)
                    mma_tf32(c[mt][nt], a[mt], b[nt]);
        }
    }

    // Epilogue: bias (+ReLU)
    #pragma unroll
    for (int mt = 0; mt < 2; ++mt) {
        const int row = m0 + wm + mt * 16 + gid;
        #pragma unroll
        for (int nt = 0; nt < 2; ++nt) {
            const int col = n0 + wn + nt * 8 + 2 * tig;
            float2 bv = *reinterpret_cast<const float2*>(&bias[col]);
            float2 v0, v1;
            v0.x = c[mt][nt][0] + bv.x;
            v0.y = c[mt][nt][1] + bv.y;
            v1.x = c[mt][nt][2] + bv.x;
            v1.y = c[mt][nt][3] + bv.y;
            if (RELU) {
                v0.x = fmaxf(v0.x, 0.f); v0.y = fmaxf(v0.y, 0.f);
                v1.x = fmaxf(v1.x, 0.f); v1.y = fmaxf(v1.y, 0.f);
            }
            *reinterpret_cast<float2*>(&C[(size_t)row * N + col]) = v0;
            *reinterpret_cast<float2*>(&C[(size_t)(row + 8) * N + col]) = v1;
        }
    }
}

extern "C" void kernel_launch(void* const* d_in, const int* in_sizes, int n_in,
                              void* d_out, int out_size)
{
    const float* nodes    = (const float*)d_in[0];
    const float* edges    = (const float*)d_in[1];
    const float* globals_ = (const float*)d_in[2];
    const int*   node_ids = (const int*)d_in[3];
    const int*   edge_ids = (const int*)d_in[4];
    const float* W1       = (const float*)d_in[5];
    const float* b1       = (const float*)d_in[6];
    const float* W2       = (const float*)d_in[7];
    const float* b2       = (const float*)d_in[8];
    float* out = (float*)d_out;

    float* collected = nullptr;
    float* hidden = nullptr;
    cudaGetSymbolAddress((void**)&collected, g_collected);
    cudaGetSymbolAddress((void**)&hidden, g_hidden);

    // Phase 0: all segment boundaries, once
    bounds_kernel<<<(2 * (N_GRAPHS + 1) + 255) / 256, 256>>>(edge_ids, node_ids);

    // Phase 1: segment sums + concat
    collect_kernel<<<8 * N_GRAPHS, 256>>>(
        (const float4*)nodes, (const float4*)edges, (const float4*)globals_,
        (float4*)collected);

    // Phase 2: hidden = relu(collected @ W1 + b1)   [1024,768]@[768,512]
    {
        dim3 grid(D_HID / 64, N_GRAPHS / 64);   // 8 x 16 = 128 CTAs
        mma_gemm<true><<<grid, 256>>>(collected, W1, b1, hidden,
                                      N_GRAPHS, D_HID, D_IN);
    }
    // Phase 3: out = hidden @ W2 + b2               [1024,512]@[512,256]
    {
        dim3 grid(D_OUT / 64, N_GRAPHS / 64);   // 4 x 16 = 64 CTAs
        mma_gemm<false><<<grid, 256>>>(hidden, W2, b2, out,
                                       N_GRAPHS, D_OUT, D_HID);
    }
}

// round 15
// speedup vs baseline: 1.0228x; 1.0228x over previous
#include <cuda_runtime.h>
#include <cstdint>

#define N_GRAPHS 1024
#define N_NODES  65536
#define N_EDGES  262144
#define D        256
#define D_IN     768
#define D_HID    512
#define D_OUT    256

// Scratch (no allocations allowed)
__device__ float g_collected[N_GRAPHS * D_IN];
__device__ float g_hidden[N_GRAPHS * D_HID];
__device__ int   g_eoff[N_GRAPHS + 1];
__device__ int   g_noff[N_GRAPHS + 1];

// ---------------------------------------------------------------------------
// Kernel 0: one-shot boundary precompute (2050 parallel binary searches).
// ---------------------------------------------------------------------------
__global__ void bounds_kernel(const int* __restrict__ eids,
                              const int* __restrict__ nids)
{
    const int t = blockIdx.x * blockDim.x + threadIdx.x;
    if (t <= N_GRAPHS) {
        int lo = 0, hi = N_EDGES;
        while (lo < hi) {
            int m = (lo + hi) >> 1;
            if (eids[m] < t) lo = m + 1; else hi = m;
        }
        g_eoff[t] = lo;
    } else if (t <= 2 * N_GRAPHS + 1) {
        const int g = t - (N_GRAPHS + 1);
        int lo = 0, hi = N_NODES;
        while (lo < hi) {
            int m = (lo + hi) >> 1;
            if (nids[m] < g) lo = m + 1; else hi = m;
        }
        g_noff[g] = lo;
    }
}

// ---------------------------------------------------------------------------
// Kernel 1: segment sums + concat. 8 CTAs/graph, precomputed bounds.
// 256 threads = 32 row-lanes x 8 float4-cols. Shuffle + smem reduce.
// ---------------------------------------------------------------------------
__global__ __launch_bounds__(256) void collect_kernel(
    const float4* __restrict__ nodes,
    const float4* __restrict__ edges,
    const float4* __restrict__ globals_,
    float4* __restrict__ collected4)
{
    const int g     = blockIdx.x >> 3;
    const int chunk = blockIdx.x & 7;
    const int t     = threadIdx.x;
    const int c     = t & 7;
    const int rl    = t >> 3;
    const int lane  = t & 31;
    const int wid   = t >> 5;
    const int colf4 = chunk * 8 + c;

    __shared__ float4 red_e[8][8];
    __shared__ float4 red_n[8][8];

    const int elo = __ldg(&g_eoff[g]), ehi = __ldg(&g_eoff[g + 1]);
    const int nlo = __ldg(&g_noff[g]), nhi = __ldg(&g_noff[g + 1]);

    float4 eacc = make_float4(0.f, 0.f, 0.f, 0.f);
    #pragma unroll 8
    for (int r = elo + rl; r < ehi; r += 32) {
        float4 v = __ldcs(&edges[(size_t)r * (D / 4) + colf4]);
        eacc.x += v.x; eacc.y += v.y; eacc.z += v.z; eacc.w += v.w;
    }
    float4 nacc = make_float4(0.f, 0.f, 0.f, 0.f);
    #pragma unroll 4
    for (int r = nlo + rl; r < nhi; r += 32) {
        float4 v = __ldcs(&nodes[(size_t)r * (D / 4) + colf4]);
        nacc.x += v.x; nacc.y += v.y; nacc.z += v.z; nacc.w += v.w;
    }

    #pragma unroll
    for (int s = 8; s <= 16; s <<= 1) {
        eacc.x += __shfl_xor_sync(0xffffffffu, eacc.x, s);
        eacc.y += __shfl_xor_sync(0xffffffffu, eacc.y, s);
        eacc.z += __shfl_xor_sync(0xffffffffu, eacc.z, s);
        eacc.w += __shfl_xor_sync(0xffffffffu, eacc.w, s);
        nacc.x += __shfl_xor_sync(0xffffffffu, nacc.x, s);
        nacc.y += __shfl_xor_sync(0xffffffffu, nacc.y, s);
        nacc.z += __shfl_xor_sync(0xffffffffu, nacc.z, s);
        nacc.w += __shfl_xor_sync(0xffffffffu, nacc.w, s);
    }
    if (lane < 8) { red_e[wid][lane] = eacc; red_n[wid][lane] = nacc; }
    __syncthreads();

    if (t < 8) {
        float4 s = red_e[0][t];
        #pragma unroll
        for (int i = 1; i < 8; ++i) {
            float4 v = red_e[i][t];
            s.x += v.x; s.y += v.y; s.z += v.z; s.w += v.w;
        }
        collected4[(size_t)g * (D_IN / 4) + chunk * 8 + t] = s;
    } else if (t < 16) {
        const int cc = t - 8;
        float4 s = red_n[0][cc];
        #pragma unroll
        for (int i = 1; i < 8; ++i) {
            float4 v = red_n[i][cc];
            s.x += v.x; s.y += v.y; s.z += v.z; s.w += v.w;
        }
        collected4[(size_t)g * (D_IN / 4) + (D / 4) + chunk * 8 + cc] = s;
    } else if (t < 24) {
        const int cc = t - 16;
        collected4[(size_t)g * (D_IN / 4) + 2 * (D / 4) + chunk * 8 + cc] =
            globals_[(size_t)g * (D / 4) + chunk * 8 + cc];
    }
}

// ---------------------------------------------------------------------------
// Kernel 2: TF32 MMA GEMM. BM=32, BN=64, BK=16, 256 threads / 8 warps in a
// 2x4 grid of 16x16 warp tiles -> per-warp instruction count per K-iter is
// halved vs 32x16 tiles, and the grid grows to 256 (GEMM1) / 128 (GEMM2)
// CTAs so >=2 CTAs land per SM. 4-stage cp.async pipeline with the
// one-commit-per-iteration invariant (empty commit at the tail).
// ---------------------------------------------------------------------------
__device__ __forceinline__ unsigned f2tf32(float x) {
    unsigned r;
    asm("cvt.rna.tf32.f32 %0, %1;" : "=r"(r) : "f"(x));
    return r;
}

__device__ __forceinline__ void mma_tf32(float (&c)[4],
                                         const unsigned (&a)[4],
                                         const unsigned (&b)[2]) {
    asm volatile(
        "mma.sync.aligned.m16n8k8.row.col.f32.tf32.tf32.f32 "
        "{%0,%1,%2,%3}, {%4,%5,%6,%7}, {%8,%9}, {%0,%1,%2,%3};\n"
        : "+f"(c[0]), "+f"(c[1]), "+f"(c[2]), "+f"(c[3])
        : "r"(a[0]), "r"(a[1]), "r"(a[2]), "r"(a[3]),
          "r"(b[0]), "r"(b[1]));
}

__device__ __forceinline__ void cp_async16(void* smem_dst, const void* gmem_src) {
    unsigned s = (unsigned)__cvta_generic_to_shared(smem_dst);
    asm volatile("cp.async.cg.shared.global [%0], [%1], 16;\n"
                 :: "r"(s), "l"(gmem_src));
}

template <bool RELU>
__global__ __launch_bounds__(256, 2) void mma_gemm(
    const float* __restrict__ A,
    const float* __restrict__ B,
    const float* __restrict__ bias,
    float* __restrict__ C,
    int M, int N, int K)
{
    constexpr int BM = 32, BN = 64, BK = 16;
    constexpr int STAGES = 4;
    constexpr int AS = BK + 4;   // 20 floats -> 80B rows (16B aligned)
    constexpr int BS = BN + 8;   // 72 floats -> 288B rows (16B aligned)
    __shared__ float As[STAGES][BM][AS];   // 10240B
    __shared__ float Bs[STAGES][BK][BS];   // 18432B  (~28KB total)

    const int tid  = threadIdx.x;
    const int wid  = tid >> 5;
    const int lane = tid & 31;
    const int gid  = lane >> 2;
    const int tig  = lane & 3;
    const int m0 = blockIdx.y * BM;
    const int n0 = blockIdx.x * BN;
    const int wm = (wid & 1) * 16;        // 2 warps along m
    const int wn = (wid >> 1) * 16;       // 4 warps along n

    float c[2][4];                         // 2 n8-frags of one 16x16 warp tile
    #pragma unroll
    for (int j = 0; j < 2; ++j)
        #pragma unroll
        for (int q = 0; q < 4; ++q) c[j][q] = 0.f;

    auto load_stage = [&](int buf, int k0) {
        // A: 32x16 f32 = 128 float4 -> threads 0..127
        if (tid < 128) {
            int r = tid >> 2, c4 = tid & 3;
            cp_async16(&As[buf][r][c4 * 4],
                       &A[(size_t)(m0 + r) * K + k0 + c4 * 4]);
        }
        // B: 16x64 f32 = 256 float4 -> 1 per thread
        {
            int r = tid >> 4, c4 = tid & 15;
            cp_async16(&Bs[buf][r][c4 * 4],
                       &B[(size_t)(k0 + r) * N + n0 + c4 * 4]);
        }
        asm volatile("cp.async.commit_group;\n" ::: "memory");
    };

    const int n_iter = K / BK;
    #pragma unroll
    for (int s = 0; s < STAGES - 1; ++s)
        load_stage(s, s * BK);            // K >= 3*BK always here

    for (int it = 0; it < n_iter; ++it) {
        asm volatile("cp.async.wait_group %0;\n" :: "n"(STAGES - 2) : "memory");
        __syncthreads();                  // stage `it` landed; prev buf free
        const int nxt = it + STAGES - 1;
        if (nxt < n_iter) {
            load_stage(nxt & (STAGES - 1), nxt * BK);
        } else {
            // Tail: preserve one-commit-per-iteration so wait_group above
            // still proves stage `it` has landed.
            asm volatile("cp.async.commit_group;\n" ::: "memory");
        }
        const int buf = it & (STAGES - 1);

        #pragma unroll
        for (int ks = 0; ks < BK; ks += 8) {
            unsigned a[4], b[2][2];
            const int rb = wm + gid;
            a[0] = f2tf32(As[buf][rb][ks + tig]);
            a[1] = f2tf32(As[buf][rb + 8][ks + tig]);
            a[2] = f2tf32(As[buf][rb][ks + tig + 4]);
            a[3] = f2tf32(As[buf][rb + 8][ks + tig + 4]);
            #pragma unroll
            for (int nt = 0; nt < 2; ++nt) {
                const int cb = wn + nt * 8 + gid;
                b[nt][0] = f2tf32(Bs[buf][ks + tig][cb]);
                b[nt][1] = f2tf32(Bs[buf][ks + tig + 4][cb]);
            }
            #pragma unroll
            for (int nt = 0; nt < 2; ++nt)
                mma_tf32(c[nt], a, b[nt]);
        }
    }

    // Epilogue: bias (+ReLU)
    {
        const int row = m0 + wm + gid;
        #pragma unroll
        for (int nt = 0; nt < 2; ++nt) {
            const int col = n0 + wn + nt * 8 + 2 * tig;
            float2 bv = *reinterpret_cast<const float2*>(&bias[col]);
            float2 v0, v1;
            v0.x = c[nt][0] + bv.x;
            v0.y = c[nt][1] + bv.y;
            v1.x = c[nt][2] + bv.x;
            v1.y = c[nt][3] + bv.y;
            if (RELU) {
                v0.x = fmaxf(v0.x, 0.f); v0.y = fmaxf(v0.y, 0.f);
                v1.x = fmaxf(v1.x, 0.f); v1.y = fmaxf(v1.y, 0.f);
            }
            *reinterpret_cast<float2*>(&C[(size_t)row * N + col]) = v0;
            *reinterpret_cast<float2*>(&C[(size_t)(row + 8) * N + col]) = v1;
        }
    }
}

extern "C" void kernel_launch(void* const* d_in, const int* in_sizes, int n_in,
                              void* d_out, int out_size)
{
    const float* nodes    = (const float*)d_in[0];
    const float* edges    = (const float*)d_in[1];
    const float* globals_ = (const float*)d_in[2];
    const int*   node_ids = (const int*)d_in[3];
    const int*   edge_ids = (const int*)d_in[4];
    const float* W1       = (const float*)d_in[5];
    const float* b1       = (const float*)d_in[6];
    const float* W2       = (const float*)d_in[7];
    const float* b2       = (const float*)d_in[8];
    float* out = (float*)d_out;

    float* collected = nullptr;
    float* hidden = nullptr;
    cudaGetSymbolAddress((void**)&collected, g_collected);
    cudaGetSymbolAddress((void**)&hidden, g_hidden);

    // Phase 0: all segment boundaries, once
    bounds_kernel<<<(2 * (N_GRAPHS + 1) + 255) / 256, 256>>>(edge_ids, node_ids);

    // Phase 1: segment sums + concat
    collect_kernel<<<8 * N_GRAPHS, 256>>>(
        (const float4*)nodes, (const float4*)edges, (const float4*)globals_,
        (float4*)collected);

    // Phase 2: hidden = relu(collected @ W1 + b1)   [1024,768]@[768,512]
    {
        dim3 grid(D_HID / 64, N_GRAPHS / 32);   // 8 x 32 = 256 CTAs
        mma_gemm<true><<<grid, 256>>>(collected, W1, b1, hidden,
                                      N_GRAPHS, D_HID, D_IN);
    }
    // Phase 3: out = hidden @ W2 + b2               [1024,512]@[512,256]
    {
        dim3 grid(D_OUT / 64, N_GRAPHS / 32);   // 4 x 32 = 128 CTAs
        mma_gemm<false><<<grid, 256>>>(hidden, W2, b2, out,
                                       N_GRAPHS, D_OUT, D_HID);
    }
}

// round 16
// speedup vs baseline: 1.0452x; 1.0219x over previous
#include <cuda_runtime.h>
#include <cstdint>

#define N_GRAPHS 1024
#define N_NODES  65536
#define N_EDGES  262144
#define D        256
#define D_IN     768
#define D_HID    512
#define D_OUT    256

// Scratch (no allocations allowed)
__device__ float g_collected[N_GRAPHS * D_IN];
__device__ float g_hidden[N_GRAPHS * D_HID];
__device__ float g_w1t[D_IN * D_HID];   // tf32-rounded W1
__device__ float g_w2t[D_HID * D_OUT];  // tf32-rounded W2
__device__ int   g_eoff[N_GRAPHS + 1];
__device__ int   g_noff[N_GRAPHS + 1];

__device__ __forceinline__ unsigned f2tf32(float x) {
    unsigned r;
    asm("cvt.rna.tf32.f32 %0, %1;" : "=r"(r) : "f"(x));
    return r;
}
__device__ __forceinline__ float rnd_tf32(float x) {
    return __uint_as_float(f2tf32(x));
}

// ---------------------------------------------------------------------------
// Kernel 0a: one-shot boundary precompute (2050 parallel binary searches).
// ---------------------------------------------------------------------------
__global__ void bounds_kernel(const int* __restrict__ eids,
                              const int* __restrict__ nids)
{
    const int t = blockIdx.x * blockDim.x + threadIdx.x;
    if (t <= N_GRAPHS) {
        int lo = 0, hi = N_EDGES;
        while (lo < hi) {
            int m = (lo + hi) >> 1;
            if (eids[m] < t) lo = m + 1; else hi = m;
        }
        g_eoff[t] = lo;
    } else if (t <= 2 * N_GRAPHS + 1) {
        const int g = t - (N_GRAPHS + 1);
        int lo = 0, hi = N_NODES;
        while (lo < hi) {
            int m = (lo + hi) >> 1;
            if (nids[m] < g) lo = m + 1; else hi = m;
        }
        g_noff[g] = lo;
    }
}

// ---------------------------------------------------------------------------
// Kernel 0b: round W1/W2 to tf32 once -> GEMM inner loops carry no cvt.
// ---------------------------------------------------------------------------
__global__ void wcvt_kernel(const float4* __restrict__ w1,
                            const float4* __restrict__ w2)
{
    const int i = blockIdx.x * blockDim.x + threadIdx.x;
    constexpr int N1 = D_IN * D_HID / 4;   // 98304
    constexpr int N2 = D_HID * D_OUT / 4;  // 32768
    if (i < N1) {
        float4 v = w1[i];
        v.x = rnd_tf32(v.x); v.y = rnd_tf32(v.y);
        v.z = rnd_tf32(v.z); v.w = rnd_tf32(v.w);
        reinterpret_cast<float4*>(g_w1t)[i] = v;
    } else if (i < N1 + N2) {
        float4 v = w2[i - N1];
        v.x = rnd_tf32(v.x); v.y = rnd_tf32(v.y);
        v.z = rnd_tf32(v.z); v.w = rnd_tf32(v.w);
        reinterpret_cast<float4*>(g_w2t)[i - N1] = v;
    }
}

// ---------------------------------------------------------------------------
// Kernel 1: segment sums + concat. 8 CTAs/graph, precomputed bounds.
// Final stores are tf32-rounded (A operand of GEMM1 pre-rounded).
// ---------------------------------------------------------------------------
__global__ __launch_bounds__(256) void collect_kernel(
    const float4* __restrict__ nodes,
    const float4* __restrict__ edges,
    const float4* __restrict__ globals_,
    float4* __restrict__ collected4)
{
    const int g     = blockIdx.x >> 3;
    const int chunk = blockIdx.x & 7;
    const int t     = threadIdx.x;
    const int c     = t & 7;
    const int rl    = t >> 3;
    const int lane  = t & 31;
    const int wid   = t >> 5;
    const int colf4 = chunk * 8 + c;

    __shared__ float4 red_e[8][8];
    __shared__ float4 red_n[8][8];

    const int elo = __ldg(&g_eoff[g]), ehi = __ldg(&g_eoff[g + 1]);
    const int nlo = __ldg(&g_noff[g]), nhi = __ldg(&g_noff[g + 1]);

    float4 eacc = make_float4(0.f, 0.f, 0.f, 0.f);
    #pragma unroll 8
    for (int r = elo + rl; r < ehi; r += 32) {
        float4 v = __ldcs(&edges[(size_t)r * (D / 4) + colf4]);
        eacc.x += v.x; eacc.y += v.y; eacc.z += v.z; eacc.w += v.w;
    }
    float4 nacc = make_float4(0.f, 0.f, 0.f, 0.f);
    #pragma unroll 4
    for (int r = nlo + rl; r < nhi; r += 32) {
        float4 v = __ldcs(&nodes[(size_t)r * (D / 4) + colf4]);
        nacc.x += v.x; nacc.y += v.y; nacc.z += v.z; nacc.w += v.w;
    }

    #pragma unroll
    for (int s = 8; s <= 16; s <<= 1) {
        eacc.x += __shfl_xor_sync(0xffffffffu, eacc.x, s);
        eacc.y += __shfl_xor_sync(0xffffffffu, eacc.y, s);
        eacc.z += __shfl_xor_sync(0xffffffffu, eacc.z, s);
        eacc.w += __shfl_xor_sync(0xffffffffu, eacc.w, s);
        nacc.x += __shfl_xor_sync(0xffffffffu, nacc.x, s);
        nacc.y += __shfl_xor_sync(0xffffffffu, nacc.y, s);
        nacc.z += __shfl_xor_sync(0xffffffffu, nacc.z, s);
        nacc.w += __shfl_xor_sync(0xffffffffu, nacc.w, s);
    }
    if (lane < 8) { red_e[wid][lane] = eacc; red_n[wid][lane] = nacc; }
    __syncthreads();

    if (t < 8) {
        float4 s = red_e[0][t];
        #pragma unroll
        for (int i = 1; i < 8; ++i) {
            float4 v = red_e[i][t];
            s.x += v.x; s.y += v.y; s.z += v.z; s.w += v.w;
        }
        s.x = rnd_tf32(s.x); s.y = rnd_tf32(s.y);
        s.z = rnd_tf32(s.z); s.w = rnd_tf32(s.w);
        collected4[(size_t)g * (D_IN / 4) + chunk * 8 + t] = s;
    } else if (t < 16) {
        const int cc = t - 8;
        float4 s = red_n[0][cc];
        #pragma unroll
        for (int i = 1; i < 8; ++i) {
            float4 v = red_n[i][cc];
            s.x += v.x; s.y += v.y; s.z += v.z; s.w += v.w;
        }
        s.x = rnd_tf32(s.x); s.y = rnd_tf32(s.y);
        s.z = rnd_tf32(s.z); s.w = rnd_tf32(s.w);
        collected4[(size_t)g * (D_IN / 4) + (D / 4) + chunk * 8 + cc] = s;
    } else if (t < 24) {
        const int cc = t - 16;
        float4 s = globals_[(size_t)g * (D / 4) + chunk * 8 + cc];
        s.x = rnd_tf32(s.x); s.y = rnd_tf32(s.y);
        s.z = rnd_tf32(s.z); s.w = rnd_tf32(s.w);
        collected4[(size_t)g * (D_IN / 4) + 2 * (D / 4) + chunk * 8 + cc] = s;
    }
}

// ---------------------------------------------------------------------------
// Kernel 2: TF32 MMA GEMM. BM=32, BN=64, BK=32, 256 threads / 8 warps
// (2x4 grid of 16x16 warp tiles). Inputs pre-rounded to tf32 -> inner loop
// is pure LDS+mma. 3-stage cp.async pipeline, one barrier per BK=32
// (half the barrier count of BK=16). Tail keeps one-commit-per-iteration.
// ROUND_OUT=true rounds the output (hidden) so GEMM2 needs no cvt either.
// ---------------------------------------------------------------------------
__device__ __forceinline__ void mma_tf32(float (&c)[4],
                                         const unsigned (&a)[4],
                                         const unsigned (&b)[2]) {
    asm volatile(
        "mma.sync.aligned.m16n8k8.row.col.f32.tf32.tf32.f32 "
        "{%0,%1,%2,%3}, {%4,%5,%6,%7}, {%8,%9}, {%0,%1,%2,%3};\n"
        : "+f"(c[0]), "+f"(c[1]), "+f"(c[2]), "+f"(c[3])
        : "r"(a[0]), "r"(a[1]), "r"(a[2]), "r"(a[3]),
          "r"(b[0]), "r"(b[1]));
}

__device__ __forceinline__ void cp_async16(void* smem_dst, const void* gmem_src) {
    unsigned s = (unsigned)__cvta_generic_to_shared(smem_dst);
    asm volatile("cp.async.cg.shared.global [%0], [%1], 16;\n"
                 :: "r"(s), "l"(gmem_src));
}

template <bool RELU, bool ROUND_OUT>
__global__ __launch_bounds__(256, 2) void mma_gemm(
    const float* __restrict__ A,
    const float* __restrict__ B,
    const float* __restrict__ bias,
    float* __restrict__ C,
    int M, int N, int K)
{
    constexpr int BM = 32, BN = 64, BK = 32;
    constexpr int STAGES = 3;
    constexpr int AS = BK + 4;   // 36 floats -> 144B rows (16B aligned)
    constexpr int BS = BN + 8;   // 72 floats -> 288B rows (16B aligned)
    __shared__ float As[STAGES][BM][AS];   // 13824B
    __shared__ float Bs[STAGES][BK][BS];   // 27648B  (~41KB total)

    const int tid  = threadIdx.x;
    const int wid  = tid >> 5;
    const int lane = tid & 31;
    const int gid  = lane >> 2;
    const int tig  = lane & 3;
    const int m0 = blockIdx.y * BM;
    const int n0 = blockIdx.x * BN;
    const int wm = (wid & 1) * 16;        // 2 warps along m
    const int wn = (wid >> 1) * 16;       // 4 warps along n

    float c[2][4];
    #pragma unroll
    for (int j = 0; j < 2; ++j)
        #pragma unroll
        for (int q = 0; q < 4; ++q) c[j][q] = 0.f;

    auto load_stage = [&](int buf, int k0) {
        // A: 32x32 f32 = 256 float4 -> 1 per thread
        {
            int r = tid >> 3, c4 = tid & 7;
            cp_async16(&As[buf][r][c4 * 4],
                       &A[(size_t)(m0 + r) * K + k0 + c4 * 4]);
        }
        // B: 32x64 f32 = 512 float4 -> 2 per thread
        #pragma unroll
        for (int p = 0; p < 2; ++p) {
            int idx = tid + p * 256;
            int r = idx >> 4, c4 = idx & 15;
            cp_async16(&Bs[buf][r][c4 * 4],
                       &B[(size_t)(k0 + r) * N + n0 + c4 * 4]);
        }
        asm volatile("cp.async.commit_group;\n" ::: "memory");
    };

    const int n_iter = K / BK;
    load_stage(0, 0);
    load_stage(1, BK);                    // K >= 2*BK always here

    int buf = 0;
    for (int it = 0; it < n_iter; ++it) {
        asm volatile("cp.async.wait_group %0;\n" :: "n"(STAGES - 2) : "memory");
        __syncthreads();                  // stage `it` landed; prev buf free
        const int nxt = it + STAGES - 1;
        if (nxt < n_iter) {
            int nbuf = buf + 2; if (nbuf >= STAGES) nbuf -= STAGES;
            load_stage(nbuf, nxt * BK);
        } else {
            // Tail: one commit per iteration keeps wait_group's guarantee.
            asm volatile("cp.async.commit_group;\n" ::: "memory");
        }

        #pragma unroll
        for (int ks = 0; ks < BK; ks += 8) {
            unsigned a[4], b[2][2];
            const int rb = wm + gid;
            a[0] = __float_as_uint(As[buf][rb][ks + tig]);
            a[1] = __float_as_uint(As[buf][rb + 8][ks + tig]);
            a[2] = __float_as_uint(As[buf][rb][ks + tig + 4]);
            a[3] = __float_as_uint(As[buf][rb + 8][ks + tig + 4]);
            #pragma unroll
            for (int nt = 0; nt < 2; ++nt) {
                const int cb = wn + nt * 8 + gid;
                b[nt][0] = __float_as_uint(Bs[buf][ks + tig][cb]);
                b[nt][1] = __float_as_uint(Bs[buf][ks + tig + 4][cb]);
            }
            #pragma unroll
            for (int nt = 0; nt < 2; ++nt)
                mma_tf32(c[nt], a, b[nt]);
        }
        if (++buf == STAGES) buf = 0;
    }

    // Epilogue: bias (+ReLU) (+tf32 rounding for the next GEMM's A operand)
    {
        const int row = m0 + wm + gid;
        #pragma unroll
        for (int nt = 0; nt < 2; ++nt) {
            const int col = n0 + wn + nt * 8 + 2 * tig;
            float2 bv = *reinterpret_cast<const float2*>(&bias[col]);
            float2 v0, v1;
            v0.x = c[nt][0] + bv.x;
            v0.y = c[nt][1] + bv.y;
            v1.x = c[nt][2] + bv.x;
            v1.y = c[nt][3] + bv.y;
            if (RELU) {
                v0.x = fmaxf(v0.x, 0.f); v0.y = fmaxf(v0.y, 0.f);
                v1.x = fmaxf(v1.x, 0.f); v1.y = fmaxf(v1.y, 0.f);
            }
            if (ROUND_OUT) {
                v0.x = rnd_tf32(v0.x); v0.y = rnd_tf32(v0.y);
                v1.x = rnd_tf32(v1.x); v1.y = rnd_tf32(v1.y);
            }
            *reinterpret_cast<float2*>(&C[(size_t)row * N + col]) = v0;
            *reinterpret_cast<float2*>(&C[(size_t)(row + 8) * N + col]) = v1;
        }
    }
}

extern "C" void kernel_launch(void* const* d_in, const int* in_sizes, int n_in,
                              void* d_out, int out_size)
{
    const float* nodes    = (const float*)d_in[0];
    const float* edges    = (const float*)d_in[1];
    const float* globals_ = (const float*)d_in[2];
    const int*   node_ids = (const int*)d_in[3];
    const int*   edge_ids = (const int*)d_in[4];
    const float* W1       = (const float*)d_in[5];
    const float* b1       = (const float*)d_in[6];
    const float* W2       = (const float*)d_in[7];
    const float* b2       = (const float*)d_in[8];
    float* out = (float*)d_out;

    float* collected = nullptr;
    float* hidden = nullptr;
    float* w1t = nullptr;
    float* w2t = nullptr;
    cudaGetSymbolAddress((void**)&collected, g_collected);
    cudaGetSymbolAddress((void**)&hidden, g_hidden);
    cudaGetSymbolAddress((void**)&w1t, g_w1t);
    cudaGetSymbolAddress((void**)&w2t, g_w2t);

    // Phase 0: boundaries + tf32-rounded weights (independent, tiny)
    bounds_kernel<<<(2 * (N_GRAPHS + 1) + 255) / 256, 256>>>(edge_ids, node_ids);
    {
        const int n4 = (D_IN * D_HID + D_HID * D_OUT) / 4;
        wcvt_kernel<<<(n4 + 255) / 256, 256>>>((const float4*)W1,
                                               (const float4*)W2);
    }

    // Phase 1: segment sums + concat (tf32-rounded output)
    collect_kernel<<<8 * N_GRAPHS, 256>>>(
        (const float4*)nodes, (const float4*)edges, (const float4*)globals_,
        (float4*)collected);

    // Phase 2: hidden = round(relu(collected @ W1 + b1))  [1024,768]@[768,512]
    {
        dim3 grid(D_HID / 64, N_GRAPHS / 32);   // 8 x 32 = 256 CTAs
        mma_gemm<true, true><<<grid, 256>>>(collected, w1t, b1, hidden,
                                            N_GRAPHS, D_HID, D_IN);
    }
    // Phase 3: out = hidden @ W2 + b2                     [1024,512]@[512,256]
    {
        dim3 grid(D_OUT / 64, N_GRAPHS / 32);   // 4 x 32 = 128 CTAs
        mma_gemm<false, false><<<grid, 256>>>(hidden, w2t, b2, out,
                                              N_GRAPHS, D_OUT, D_HID);
    }
}

// round 17
// speedup vs baseline: 1.1212x; 1.0727x over previous
#include <cuda_runtime.h>
#include <cstdint>

#define N_GRAPHS 1024
#define N_NODES  65536
#define N_EDGES  262144
#define D        256
#define D_IN     768
#define D_HID    512
#define D_OUT    256

// Scratch (no allocations allowed)
__device__ float g_collected[N_GRAPHS * D_IN];
__device__ float g_hidden[N_GRAPHS * D_HID];
__device__ float g_w1t[D_IN * D_HID];   // tf32-rounded W1
__device__ float g_w2t[D_HID * D_OUT];  // tf32-rounded W2
__device__ int   g_eoff[N_GRAPHS + 1];
__device__ int   g_noff[N_GRAPHS + 1];

__device__ __forceinline__ unsigned f2tf32(float x) {
    unsigned r;
    asm("cvt.rna.tf32.f32 %0, %1;" : "=r"(r) : "f"(x));
    return r;
}
__device__ __forceinline__ float rnd_tf32(float x) {
    return __uint_as_float(f2tf32(x));
}

// ---------------------------------------------------------------------------
// Kernel 0: fused prep — tf32-round W1/W2 (bulk) + 2050 binary searches.
// One launch instead of two (the stream is serial; every launch costs).
// ---------------------------------------------------------------------------
__global__ void prep_kernel(const float4* __restrict__ w1,
                            const float4* __restrict__ w2,
                            const int* __restrict__ eids,
                            const int* __restrict__ nids)
{
    const int i = blockIdx.x * blockDim.x + threadIdx.x;
    constexpr int N1 = D_IN * D_HID / 4;   // 98304
    constexpr int N2 = D_HID * D_OUT / 4;  // 32768
    if (i < N1) {
        float4 v = w1[i];
        v.x = rnd_tf32(v.x); v.y = rnd_tf32(v.y);
        v.z = rnd_tf32(v.z); v.w = rnd_tf32(v.w);
        reinterpret_cast<float4*>(g_w1t)[i] = v;
    } else if (i < N1 + N2) {
        float4 v = w2[i - N1];
        v.x = rnd_tf32(v.x); v.y = rnd_tf32(v.y);
        v.z = rnd_tf32(v.z); v.w = rnd_tf32(v.w);
        reinterpret_cast<float4*>(g_w2t)[i - N1] = v;
    } else {
        const int t = i - (N1 + N2);
        if (t <= N_GRAPHS) {
            int lo = 0, hi = N_EDGES;
            while (lo < hi) {
                int m = (lo + hi) >> 1;
                if (eids[m] < t) lo = m + 1; else hi = m;
            }
            g_eoff[t] = lo;
        } else if (t <= 2 * N_GRAPHS + 1) {
            const int g = t - (N_GRAPHS + 1);
            int lo = 0, hi = N_NODES;
            while (lo < hi) {
                int m = (lo + hi) >> 1;
                if (nids[m] < g) lo = m + 1; else hi = m;
            }
            g_noff[g] = lo;
        }
    }
}

// ---------------------------------------------------------------------------
// Kernel 1: segment sums + concat. 8 CTAs/graph, precomputed bounds.
// Final stores tf32-rounded (GEMM1's A operand pre-rounded).
// ---------------------------------------------------------------------------
__global__ __launch_bounds__(256) void collect_kernel(
    const float4* __restrict__ nodes,
    const float4* __restrict__ edges,
    const float4* __restrict__ globals_,
    float4* __restrict__ collected4)
{
    const int g     = blockIdx.x >> 3;
    const int chunk = blockIdx.x & 7;
    const int t     = threadIdx.x;
    const int c     = t & 7;
    const int rl    = t >> 3;
    const int lane  = t & 31;
    const int wid   = t >> 5;
    const int colf4 = chunk * 8 + c;

    __shared__ float4 red_e[8][8];
    __shared__ float4 red_n[8][8];

    const int elo = __ldg(&g_eoff[g]), ehi = __ldg(&g_eoff[g + 1]);
    const int nlo = __ldg(&g_noff[g]), nhi = __ldg(&g_noff[g + 1]);

    float4 eacc = make_float4(0.f, 0.f, 0.f, 0.f);
    #pragma unroll 8
    for (int r = elo + rl; r < ehi; r += 32) {
        float4 v = __ldcs(&edges[(size_t)r * (D / 4) + colf4]);
        eacc.x += v.x; eacc.y += v.y; eacc.z += v.z; eacc.w += v.w;
    }
    float4 nacc = make_float4(0.f, 0.f, 0.f, 0.f);
    #pragma unroll 4
    for (int r = nlo + rl; r < nhi; r += 32) {
        float4 v = __ldcs(&nodes[(size_t)r * (D / 4) + colf4]);
        nacc.x += v.x; nacc.y += v.y; nacc.z += v.z; nacc.w += v.w;
    }

    #pragma unroll
    for (int s = 8; s <= 16; s <<= 1) {
        eacc.x += __shfl_xor_sync(0xffffffffu, eacc.x, s);
        eacc.y += __shfl_xor_sync(0xffffffffu, eacc.y, s);
        eacc.z += __shfl_xor_sync(0xffffffffu, eacc.z, s);
        eacc.w += __shfl_xor_sync(0xffffffffu, eacc.w, s);
        nacc.x += __shfl_xor_sync(0xffffffffu, nacc.x, s);
        nacc.y += __shfl_xor_sync(0xffffffffu, nacc.y, s);
        nacc.z += __shfl_xor_sync(0xffffffffu, nacc.z, s);
        nacc.w += __shfl_xor_sync(0xffffffffu, nacc.w, s);
    }
    if (lane < 8) { red_e[wid][lane] = eacc; red_n[wid][lane] = nacc; }
    __syncthreads();

    if (t < 8) {
        float4 s = red_e[0][t];
        #pragma unroll
        for (int i = 1; i < 8; ++i) {
            float4 v = red_e[i][t];
            s.x += v.x; s.y += v.y; s.z += v.z; s.w += v.w;
        }
        s.x = rnd_tf32(s.x); s.y = rnd_tf32(s.y);
        s.z = rnd_tf32(s.z); s.w = rnd_tf32(s.w);
        collected4[(size_t)g * (D_IN / 4) + chunk * 8 + t] = s;
    } else if (t < 16) {
        const int cc = t - 8;
        float4 s = red_n[0][cc];
        #pragma unroll
        for (int i = 1; i < 8; ++i) {
            float4 v = red_n[i][cc];
            s.x += v.x; s.y += v.y; s.z += v.z; s.w += v.w;
        }
        s.x = rnd_tf32(s.x); s.y = rnd_tf32(s.y);
        s.z = rnd_tf32(s.z); s.w = rnd_tf32(s.w);
        collected4[(size_t)g * (D_IN / 4) + (D / 4) + chunk * 8 + cc] = s;
    } else if (t < 24) {
        const int cc = t - 16;
        float4 s = globals_[(size_t)g * (D / 4) + chunk * 8 + cc];
        s.x = rnd_tf32(s.x); s.y = rnd_tf32(s.y);
        s.z = rnd_tf32(s.z); s.w = rnd_tf32(s.w);
        collected4[(size_t)g * (D_IN / 4) + 2 * (D / 4) + chunk * 8 + cc] = s;
    }
}

// ---------------------------------------------------------------------------
// Kernel 2: TF32 MMA GEMM. 128 threads / 4 warps in 2x2, warp tile
// 32 x (NT*8). BM=64, BN=NT*16, BK=32 -> per warp-ks8: 8 A-LDS + 2*NT B-LDS
// + 2*NT mma (2 LDS per mma at NT=4). Inputs pre-rounded to tf32 (no cvt in
// loop). 3-stage cp.async pipeline, one commit per iteration (empty at tail).
// ---------------------------------------------------------------------------
__device__ __forceinline__ void mma_tf32(float (&c)[4],
                                         const unsigned (&a)[4],
                                         const unsigned (&b)[2]) {
    asm volatile(
        "mma.sync.aligned.m16n8k8.row.col.f32.tf32.tf32.f32 "
        "{%0,%1,%2,%3}, {%4,%5,%6,%7}, {%8,%9}, {%0,%1,%2,%3};\n"
        : "+f"(c[0]), "+f"(c[1]), "+f"(c[2]), "+f"(c[3])
        : "r"(a[0]), "r"(a[1]), "r"(a[2]), "r"(a[3]),
          "r"(b[0]), "r"(b[1]));
}

__device__ __forceinline__ void cp_async16(void* smem_dst, const void* gmem_src) {
    unsigned s = (unsigned)__cvta_generic_to_shared(smem_dst);
    asm volatile("cp.async.cg.shared.global [%0], [%1], 16;\n"
                 :: "r"(s), "l"(gmem_src));
}

template <bool RELU, bool ROUND_OUT, int NT>
__global__ __launch_bounds__(128, 2) void mma_gemm(
    const float* __restrict__ A,
    const float* __restrict__ B,
    const float* __restrict__ bias,
    float* __restrict__ C,
    int M, int N, int K)
{
    constexpr int BM = 64, BN = NT * 16, BK = 32;
    constexpr int STAGES = 3;
    constexpr int AS = BK + 4;    // 36 floats/row (144B, 16B aligned)
    constexpr int BS = BN + 8;    // NT=4: 72; NT=2: 40 (both 16B aligned)
    constexpr int BF4 = BN / 4;   // float4 per B row
    __shared__ float As[STAGES][BM][AS];
    __shared__ float Bs[STAGES][BK][BS];

    const int tid  = threadIdx.x;
    const int wid  = tid >> 5;
    const int lane = tid & 31;
    const int gid  = lane >> 2;
    const int tig  = lane & 3;
    const int m0 = blockIdx.y * BM;
    const int n0 = blockIdx.x * BN;
    const int wm = (wid & 1) * 32;        // 2 warps along m (32-row tiles)
    const int wn = (wid >> 1) * (NT * 8); // 2 warps along n

    float c[2][NT][4];
    #pragma unroll
    for (int i = 0; i < 2; ++i)
        #pragma unroll
        for (int j = 0; j < NT; ++j)
            #pragma unroll
            for (int q = 0; q < 4; ++q) c[i][j][q] = 0.f;

    auto load_stage = [&](int buf, int k0) {
        // A: 64x32 f32 = 512 float4 -> 4 per thread
        #pragma unroll
        for (int p = 0; p < 4; ++p) {
            int idx = tid + p * 128;
            int r = idx >> 3, c4 = idx & 7;
            cp_async16(&As[buf][r][c4 * 4],
                       &A[(size_t)(m0 + r) * K + k0 + c4 * 4]);
        }
        // B: 32xBN f32 = 8*BF4 float4 -> BF4/4 per thread
        #pragma unroll
        for (int p = 0; p < BF4 / 4; ++p) {
            int idx = tid + p * 128;
            int r = idx / BF4, c4 = idx % BF4;
            cp_async16(&Bs[buf][r][c4 * 4],
                       &B[(size_t)(k0 + r) * N + n0 + c4 * 4]);
        }
        asm volatile("cp.async.commit_group;\n" ::: "memory");
    };

    const int n_iter = K / BK;
    load_stage(0, 0);
    load_stage(1, BK);                    // K >= 2*BK always here

    int buf = 0;
    for (int it = 0; it < n_iter; ++it) {
        asm volatile("cp.async.wait_group %0;\n" :: "n"(STAGES - 2) : "memory");
        __syncthreads();                  // stage `it` landed; prev buf free
        const int nxt = it + STAGES - 1;
        if (nxt < n_iter) {
            int nbuf = buf + 2; if (nbuf >= STAGES) nbuf -= STAGES;
            load_stage(nbuf, nxt * BK);
        } else {
            // Tail: one commit per iteration keeps wait_group's guarantee.
            asm volatile("cp.async.commit_group;\n" ::: "memory");
        }

        #pragma unroll
        for (int ks = 0; ks < BK; ks += 8) {
            unsigned a[2][4], b[NT][2];
            #pragma unroll
            for (int mt = 0; mt < 2; ++mt) {
                const int rb = wm + mt * 16 + gid;
                a[mt][0] = __float_as_uint(As[buf][rb][ks + tig]);
                a[mt][1] = __float_as_uint(As[buf][rb + 8][ks + tig]);
                a[mt][2] = __float_as_uint(As[buf][rb][ks + tig + 4]);
                a[mt][3] = __float_as_uint(As[buf][rb + 8][ks + tig + 4]);
            }
            #pragma unroll
            for (int nt = 0; nt < NT; ++nt) {
                const int cb = wn + nt * 8 + gid;
                b[nt][0] = __float_as_uint(Bs[buf][ks + tig][cb]);
                b[nt][1] = __float_as_uint(Bs[buf][ks + tig + 4][cb]);
            }
            #pragma unroll
            for (int mt = 0; mt < 2; ++mt)
                #pragma unroll
                for (int nt = 0; nt < NT; ++nt)
                    mma_tf32(c[mt][nt], a[mt], b[nt]);
        }
        if (++buf == STAGES) buf = 0;
    }

    // Epilogue: bias (+ReLU) (+tf32 rounding when feeding the next GEMM)
    #pragma unroll
    for (int mt = 0; mt < 2; ++mt) {
        const int row = m0 + wm + mt * 16 + gid;
        #pragma unroll
        for (int nt = 0; nt < NT; ++nt) {
            const int col = n0 + wn + nt * 8 + 2 * tig;
            float2 bv = *reinterpret_cast<const float2*>(&bias[col]);
            float2 v0, v1;
            v0.x = c[mt][nt][0] + bv.x;
            v0.y = c[mt][nt][1] + bv.y;
            v1.x = c[mt][nt][2] + bv.x;
            v1.y = c[mt][nt][3] + bv.y;
            if (RELU) {
                v0.x = fmaxf(v0.x, 0.f); v0.y = fmaxf(v0.y, 0.f);
                v1.x = fmaxf(v1.x, 0.f); v1.y = fmaxf(v1.y, 0.f);
            }
            if (ROUND_OUT) {
                v0.x = rnd_tf32(v0.x); v0.y = rnd_tf32(v0.y);
                v1.x = rnd_tf32(v1.x); v1.y = rnd_tf32(v1.y);
            }
            *reinterpret_cast<float2*>(&C[(size_t)row * N + col]) = v0;
            *reinterpret_cast<float2*>(&C[(size_t)(row + 8) * N + col]) = v1;
        }
    }
}

extern "C" void kernel_launch(void* const* d_in, const int* in_sizes, int n_in,
                              void* d_out, int out_size)
{
    const float* nodes    = (const float*)d_in[0];
    const float* edges    = (const float*)d_in[1];
    const float* globals_ = (const float*)d_in[2];
    const int*   node_ids = (const int*)d_in[3];
    const int*   edge_ids = (const int*)d_in[4];
    const float* W1       = (const float*)d_in[5];
    const float* b1       = (const float*)d_in[6];
    const float* W2       = (const float*)d_in[7];
    const float* b2       = (const float*)d_in[8];
    float* out = (float*)d_out;

    float* collected = nullptr;
    float* hidden = nullptr;
    float* w1t = nullptr;
    float* w2t = nullptr;
    cudaGetSymbolAddress((void**)&collected, g_collected);
    cudaGetSymbolAddress((void**)&hidden, g_hidden);
    cudaGetSymbolAddress((void**)&w1t, g_w1t);
    cudaGetSymbolAddress((void**)&w2t, g_w2t);

    // Phase 0: fused weight-rounding + boundary search (single launch)
    {
        const int total = (D_IN * D_HID + D_HID * D_OUT) / 4
                          + 2 * (N_GRAPHS + 1);
        prep_kernel<<<(total + 255) / 256, 256>>>(
            (const float4*)W1, (const float4*)W2, edge_ids, node_ids);
    }

    // Phase 1: segment sums + concat (tf32-rounded output)
    collect_kernel<<<8 * N_GRAPHS, 256>>>(
        (const float4*)nodes, (const float4*)edges, (const float4*)globals_,
        (float4*)collected);

    // Phase 2: hidden = round(relu(collected @ W1 + b1))  [1024,768]@[768,512]
    {
        dim3 grid(D_HID / 64, N_GRAPHS / 64);   // 8 x 16 = 128 CTAs, 1 wave
        mma_gemm<true, true, 4><<<grid, 128>>>(collected, w1t, b1, hidden,
                                               N_GRAPHS, D_HID, D_IN);
    }
    // Phase 3: out = hidden @ W2 + b2                     [1024,512]@[512,256]
    {
        dim3 grid(D_OUT / 32, N_GRAPHS / 64);   // 8 x 16 = 128 CTAs, 1 wave
        mma_gemm<false, false, 2><<<grid, 128>>>(hidden, w2t, b2, out,
                                                 N_GRAPHS, D_OUT, D_HID);
    }
}